// round 12
// baseline (speedup 1.0000x reference)
#include <cuda_runtime.h>
#include <cuda_fp16.h>
#include <cstdint>
#include <math.h>

// ---------------- problem constants ----------------------------------------
#define D_IN   512
#define HID    1024
#define SEQ    4096
#define BATCH  4
#define CHUNK  256
#define NCHUNK 16
#define ROWS_TOTAL (BATCH*SEQ)     // 16384
#define ROWS_CHUNK (BATCH*CHUNK)   // 1024
#define WSZ    (D_IN*HID)          // 524288
#define NB     148

// ---------------- scratch (device globals) ----------------------------------
__device__ float g_V [ROWS_TOTAL*D_IN];   // chunk-major f32
__device__ float g_H [ROWS_CHUNK*HID];    // pre-gelu f32
__device__ float g_W1[WSZ], g_W2[WSZ], g_S1[WSZ], g_S2[WSZ];
__device__ unsigned g_grp[8*32];          // 8 group counters, 128B apart
__device__ unsigned g_root;
__device__ unsigned g_epochflag;

__device__ __half g_xh [ROWS_TOTAL*D_IN];
__device__ __half g_Qh [ROWS_TOTAL*D_IN];
__device__ __half g_Kh [ROWS_TOTAL*D_IN];        // chunk-major
__device__ __half g_W1h[WSZ];
__device__ __half g_W2hA[WSZ], g_W2hB[WSZ];      // hi ping-pong
__device__ __half g_Ah [ROWS_CHUNK*HID];
__device__ __half g_Eh [ROWS_CHUNK*D_IN];
__device__ __half g_dHh[ROWS_CHUNK*HID];
__device__ __half g_Hqh[ROWS_TOTAL*HID];
__device__ __half g_wqh[D_IN*D_IN], g_wkh[D_IN*D_IN], g_wvh[D_IN*D_IN];

// ---------------- math helpers ----------------------------------------------
__device__ __forceinline__ float gelu_f(float x) {
    return 0.5f * x * (1.0f + erff(x * 0.70710678118654752f));
}
__device__ __forceinline__ float gelu_grad_f(float x) {
    float cdf = 0.5f * (1.0f + erff(x * 0.70710678118654752f));
    float pdf = 0.3989422804014327f * __expf(-0.5f * x * x);
    return cdf + x * pdf;
}
__device__ __forceinline__ float sigmoid_f(float x) {
    return 1.0f / (1.0f + __expf(-x));
}
__device__ __forceinline__ uint32_t pack_h2(float v0, float v1) {
    __half2 hh = __floats2half2_rn(v0, v1);
    return *(uint32_t*)&hh;
}

// ---------------- PTX helpers ------------------------------------------------
__device__ __forceinline__ uint32_t smem_u32(const void* p) {
    uint32_t a;
    asm("{ .reg .u64 t; cvta.to.shared.u64 t, %1; cvt.u32.u64 %0, t; }" : "=r"(a) : "l"(p));
    return a;
}
__device__ __forceinline__ void cp16(uint32_t d, const void* s) {
    asm volatile("cp.async.cg.shared.global [%0], [%1], 16;" :: "r"(d), "l"(s));
}
__device__ __forceinline__ void ldsm4(uint32_t a, uint32_t& r0, uint32_t& r1,
                                      uint32_t& r2, uint32_t& r3) {
    asm volatile("ldmatrix.sync.aligned.m8n8.x4.shared.b16 {%0,%1,%2,%3}, [%4];"
                 : "=r"(r0), "=r"(r1), "=r"(r2), "=r"(r3) : "r"(a));
}
__device__ __forceinline__ void ldsm4t(uint32_t a, uint32_t& r0, uint32_t& r1,
                                       uint32_t& r2, uint32_t& r3) {
    asm volatile("ldmatrix.sync.aligned.m8n8.x4.trans.shared.b16 {%0,%1,%2,%3}, [%4];"
                 : "=r"(r0), "=r"(r1), "=r"(r2), "=r"(r3) : "r"(a));
}
__device__ __forceinline__ void mma16816(float* c, const uint32_t* a, const uint32_t* b) {
    asm volatile(
        "mma.sync.aligned.m16n8k16.row.col.f32.f16.f16.f32 "
        "{%0,%1,%2,%3}, {%4,%5,%6,%7}, {%8,%9}, {%0,%1,%2,%3};"
        : "+f"(c[0]), "+f"(c[1]), "+f"(c[2]), "+f"(c[3])
        : "r"(a[0]), "r"(a[1]), "r"(a[2]), "r"(a[3]), "r"(b[0]), "r"(b[1]));
}

#define P_SMEM3   98304   // chunk loop: 3 stages * 32KB (BM=128 path)
#define P_SMEM_O  98304   // outer: 3 stages * 32KB (BM=128)

// ============================================================================
// 1-term fp16 tile GEMM, BK=64, NS-stage cp.async pipeline, 8 warps.
// BM=32/64: warps 2m x 4n (warp tile (BM/2) x 32)  — latency-optimized.
// BM=128:  warps 4m x 2n (warp tile 32 x 64)       — throughput-optimized.
// K-summation order per output element identical across BM choices.
// EPI: 0 C=v f32 | 1 Ch=h(v) | 3 C=v f32, Ch=h(gelu(v)) | 4 Ch=h((v-aux)*scale)
//      5 Ch=h(v*gelu'(aux)) | 6 momentum: s=decay*S-lr*v; S=s; w=om*C+s; C=w; Ch=h(w)
//      7 perm, Ch=h(v) | 8 perm, C=v f32 | 9 Ch=h(gelu(v))
// ============================================================================
template<int BM, int NS, bool TA, bool TB, int EPI>
__device__ __forceinline__ void tile_gemm(
    const __half* __restrict__ A_, int lda,
    const __half* __restrict__ B_, int ldb,
    int K, int m0, int n0, uint32_t sbase,
    float* __restrict__ C, __half* __restrict__ Ch, int ldc,
    const float* __restrict__ aux, float scale,
    float decay, float lr, float om, float* __restrict__ S)
{
    constexpr int A_T = BM * 128;        // BM x 64 halfs (bytes)
    constexpr int B_T = 16384;           // 128 x 64 halfs
    constexpr int BUF = A_T + B_T;
    constexpr int MWARPS = (BM == 128) ? 4 : 2;
    constexpr int NWARPS = 8 / MWARPS;
    constexpr int WN  = 128 / NWARPS;    // 32 or 64
    constexpr int NF  = WN / 8;          // 4 or 8
    constexpr int BJ  = NF / 2;          // 2 or 4
    constexpr int MT  = (BM / MWARPS) / 16;  // 1 (BM=32) or 2
    constexpr int ACP = BM / 32;         // A cp16 per thread

    const int tid = threadIdx.x, wid = tid >> 5, lane = tid & 31;
    const int wm = (wid % MWARPS) * (BM / MWARPS);
    const int wn = (wid / MWARPS) * WN;

    float acc[MT][NF][4];
    #pragma unroll
    for (int a = 0; a < MT; a++)
        #pragma unroll
        for (int b = 0; b < NF; b++)
            #pragma unroll
            for (int d = 0; d < 4; d++) acc[a][b][d] = 0.f;

    // ---- A staging ----
    const __half* srcA[ACP];
    uint32_t dA[ACP];
    #pragma unroll
    for (int i = 0; i < ACP; i++) {
        int idx = tid + i * 256;
        if (!TA) {
            int r = idx >> 3, kq = idx & 7;
            srcA[i] = A_ + (size_t)(m0 + r) * lda + kq * 8;
            dA[i] = r * 128 + ((kq ^ (r & 7)) << 4);
        } else {
            if (BM >= 64) {
                int kr = idx & 63, rq = idx >> 6;   // 64 k-rows, BM/8 groups
                srcA[i] = A_ + (size_t)kr * lda + m0 + rq * 8;
                dA[i] = kr * (BM * 2) + ((rq ^ (kr & (BM/8 - 1))) << 4);
            } else {
                int kr = idx >> 2, rq = idx & 3;
                srcA[i] = A_ + (size_t)kr * lda + m0 + rq * 8;
                dA[i] = kr * 64 + ((rq ^ (kr & 3)) << 4);
            }
        }
    }
    const size_t advA = TA ? (size_t)64 * lda : 64;

    // ---- B staging (4 cp16 per thread) ----
    const __half* srcB[4];
    uint32_t dB[4];
    #pragma unroll
    for (int i = 0; i < 4; i++) {
        int fi = tid + i * 256;
        if (!TB) {
            int kr = fi >> 4, rq = fi & 15;
            srcB[i] = B_ + (size_t)kr * ldb + n0 + rq * 8;
            dB[i] = A_T + kr * 256 + ((rq ^ (kr & 7)) << 4);
        } else {
            int r = fi >> 3, kq = fi & 7;
            srcB[i] = B_ + (size_t)(n0 + r) * ldb + kq * 8;
            dB[i] = A_T + r * 128 + ((kq ^ (r & 7)) << 4);
        }
    }
    const size_t advB = TB ? 64 : (size_t)64 * ldb;

    // ---- ldmatrix addresses (s = 0..3 k16-steps within BK=64) ----
    uint32_t aA[4][MT], aB[4][BJ];
    #pragma unroll
    for (int s = 0; s < 4; s++) {
        #pragma unroll
        for (int mt = 0; mt < MT; mt++) {
            if (!TA) {
                int r = wm + mt * 16 + (lane & 15);
                int g = 2 * s + (lane >> 4);
                aA[s][mt] = r * 128 + ((g ^ (r & 7)) << 4);
            } else {
                int k = 16 * s + (lane & 7) + (lane >> 4) * 8;
                int mg = ((wm + mt * 16) >> 3) + ((lane >> 3) & 1);
                aA[s][mt] = (BM >= 64) ? k * (BM * 2) + ((mg ^ (k & (BM/8 - 1))) << 4)
                                       : k * 64 + ((mg ^ (k & 3)) << 4);
            }
        }
        #pragma unroll
        for (int j = 0; j < BJ; j++) {
            if (!TB) {
                int k = 16 * s + (lane & 7) + ((lane >> 3) & 1) * 8;
                int ng = ((wn + j * 16) >> 3) + (lane >> 4);
                aB[s][j] = A_T + k * 256 + ((ng ^ (k & 7)) << 4);
            } else {
                int n = wn + j * 16 + (lane & 7) + (lane >> 4) * 8;
                int g = 2 * s + ((lane >> 3) & 1);
                aB[s][j] = A_T + n * 128 + ((g ^ (n & 7)) << 4);
            }
        }
    }

    const int NC = K >> 6;

    auto issue = [&](int c, int buf) {
        uint32_t b = sbase + buf * BUF;
        #pragma unroll
        for (int i = 0; i < ACP; i++) cp16(b + dA[i], srcA[i] + c * advA);
        #pragma unroll
        for (int i = 0; i < 4;   i++) cp16(b + dB[i], srcB[i] + c * advB);
        asm volatile("cp.async.commit_group;");
    };

    uint32_t FA[2][MT][4], FB[2][NF][2];
    auto load_frags = [&](int s, uint32_t bb, int p) {
        #pragma unroll
        for (int mt = 0; mt < MT; mt++) {
            if (!TA) ldsm4 (bb + aA[s][mt], FA[p][mt][0], FA[p][mt][1], FA[p][mt][2], FA[p][mt][3]);
            else     ldsm4t(bb + aA[s][mt], FA[p][mt][0], FA[p][mt][1], FA[p][mt][2], FA[p][mt][3]);
        }
        #pragma unroll
        for (int j = 0; j < BJ; j++) {
            if (!TB) ldsm4t(bb + aB[s][j], FB[p][2*j][0], FB[p][2*j][1], FB[p][2*j+1][0], FB[p][2*j+1][1]);
            else     ldsm4 (bb + aB[s][j], FB[p][2*j][0], FB[p][2*j][1], FB[p][2*j+1][0], FB[p][2*j+1][1]);
        }
    };

    issue(0, 0);
    if (NS == 3) issue(1, 1);
    for (int c = 0; c < NC; c++) {
        if (NS == 3) {
            if (c < NC - 1) asm volatile("cp.async.wait_group 1;");
            else            asm volatile("cp.async.wait_group 0;");
            __syncthreads();
            if (c + 2 < NC) issue(c + 2, (c + 2) % 3);
        } else {
            if (c + 1 < NC) {
                issue(c + 1, (c + 1) & 1);
                asm volatile("cp.async.wait_group 1;");
            } else {
                asm volatile("cp.async.wait_group 0;");
            }
            __syncthreads();
        }

        const uint32_t bb = sbase + (c % NS) * BUF;
        load_frags(0, bb, 0);
        #pragma unroll
        for (int s = 0; s < 4; s++) {
            int p = s & 1;
            if (s < 3) load_frags(s + 1, bb, p ^ 1);
            #pragma unroll
            for (int mt = 0; mt < MT; mt++)
                #pragma unroll
                for (int nt = 0; nt < NF; nt++)
                    mma16816(acc[mt][nt], FA[p][mt], FB[p][nt]);
        }
        if (NS == 2) __syncthreads();
    }
    if (NS == 3) __syncthreads();       // protect smem reuse by caller's next tile

    // ---- epilogue ----
    #pragma unroll
    for (int mt = 0; mt < MT; mt++) {
        #pragma unroll
        for (int half = 0; half < 2; half++) {
            int r = m0 + wm + mt * 16 + (lane >> 2) + half * 8;
            #pragma unroll
            for (int nt = 0; nt < NF; nt++) {
                int cc = n0 + wn + nt * 8 + 2 * (lane & 3);
                float v0 = acc[mt][nt][half * 2 + 0];
                float v1 = acc[mt][nt][half * 2 + 1];
                size_t idx = (size_t)r * ldc + cc;
                if (EPI == 0) {
                    *(float2*)(C + idx) = make_float2(v0, v1);
                } else if (EPI == 1) {
                    *(uint32_t*)(Ch + idx) = pack_h2(v0, v1);
                } else if (EPI == 3) {
                    *(float2*)(C + idx) = make_float2(v0, v1);
                    *(uint32_t*)(Ch + idx) = pack_h2(gelu_f(v0), gelu_f(v1));
                } else if (EPI == 4) {
                    float2 a2 = *(const float2*)(aux + idx);
                    *(uint32_t*)(Ch + idx) = pack_h2((v0 - a2.x) * scale, (v1 - a2.y) * scale);
                } else if (EPI == 5) {
                    float2 a2 = *(const float2*)(aux + idx);
                    *(uint32_t*)(Ch + idx) = pack_h2(v0 * gelu_grad_f(a2.x), v1 * gelu_grad_f(a2.y));
                } else if (EPI == 6) {
                    float2 w = *(const float2*)(C + idx);
                    float2 s = *(const float2*)(S + idx);
                    float s0 = decay * s.x - lr * v0;
                    float s1 = decay * s.y - lr * v1;
                    float w0 = om * w.x + s0, w1 = om * w.y + s1;
                    *(float2*)(S + idx) = make_float2(s0, s1);
                    *(float2*)(C + idx) = make_float2(w0, w1);
                    *(uint32_t*)(Ch + idx) = pack_h2(w0, w1);
                } else if (EPI == 7) {
                    int b = r >> 12, sq = r & 4095, chn = sq >> 8, t = sq & 255;
                    size_t orow = (size_t)(chn * 1024 + b * 256 + t) * ldc + cc;
                    *(uint32_t*)(Ch + orow) = pack_h2(v0, v1);
                } else if (EPI == 8) {
                    int b = r >> 12, sq = r & 4095, chn = sq >> 8, t = sq & 255;
                    size_t orow = (size_t)(chn * 1024 + b * 256 + t) * ldc + cc;
                    *(float2*)(C + orow) = make_float2(v0, v1);
                } else { // EPI == 9
                    *(uint32_t*)(Ch + idx) = pack_h2(gelu_f(v0), gelu_f(v1));
                }
            }
        }
    }
}

// ---------------- standalone wrappers (BM=128 throughput tiles) ---------------
__global__ void __launch_bounds__(256) qkv_kernel() {
    extern __shared__ char smem[];
    const uint32_t sbase = smem_u32(smem);
    int m0 = blockIdx.y * 128, n0 = blockIdx.x * 128;
    int z = blockIdx.z;
    if (z == 0)
        tile_gemm<128,3,false,false,1>(g_xh, D_IN, g_wqh, D_IN, D_IN,
            m0, n0, sbase, nullptr, g_Qh, D_IN, nullptr, 0.f, 0.f, 0.f, 0.f, nullptr);
    else if (z == 1)
        tile_gemm<128,3,false,false,7>(g_xh, D_IN, g_wkh, D_IN, D_IN,
            m0, n0, sbase, nullptr, g_Kh, D_IN, nullptr, 0.f, 0.f, 0.f, 0.f, nullptr);
    else
        tile_gemm<128,3,false,false,8>(g_xh, D_IN, g_wvh, D_IN, D_IN,
            m0, n0, sbase, g_V, nullptr, D_IN, nullptr, 0.f, 0.f, 0.f, 0.f, nullptr);
}

__global__ void __launch_bounds__(256) ro1_kernel() {
    extern __shared__ char smem[];
    const uint32_t sbase = smem_u32(smem);
    tile_gemm<128,3,false,false,9>(g_Qh, D_IN, g_W1h, HID, D_IN,
        blockIdx.y * 128, blockIdx.x * 128, sbase,
        nullptr, g_Hqh, HID, nullptr, 0.f, 0.f, 0.f, 0.f, nullptr);
}

__global__ void __launch_bounds__(256) ro2_kernel(float* __restrict__ out) {
    extern __shared__ char smem[];
    const uint32_t sbase = smem_u32(smem);
    tile_gemm<128,3,false,false,0>(g_Hqh, HID, g_W2hA, D_IN, HID,
        blockIdx.y * 128, blockIdx.x * 128, sbase,
        out, nullptr, D_IN, nullptr, 0.f, 0.f, 0.f, 0.f, nullptr);
}

// ---------------- hierarchical grid barrier ----------------------------------
__device__ __forceinline__ void gsync(unsigned& epoch) {
    __syncthreads();
    if (threadIdx.x == 0) {
        epoch++;
        const unsigned grp = blockIdx.x & 7u;
        const unsigned gsz = (grp < 4u) ? 19u : 18u;   // 4*19 + 4*18 = 148
        unsigned prev;
        asm volatile("atom.add.acq_rel.gpu.u32 %0, [%1], 1;"
                     : "=r"(prev) : "l"(&g_grp[grp * 32]) : "memory");
        if (prev + 1u == epoch * gsz) {
            unsigned rprev;
            asm volatile("atom.add.acq_rel.gpu.u32 %0, [%1], 1;"
                         : "=r"(rprev) : "l"(&g_root) : "memory");
            if (rprev + 1u == epoch * 8u) {
                asm volatile("st.release.gpu.u32 [%0], %1;"
                             :: "l"(&g_epochflag), "r"(epoch) : "memory");
            }
        }
        unsigned e;
        do {
            asm volatile("ld.acquire.gpu.u32 %0, [%1];"
                         : "=r"(e) : "l"(&g_epochflag) : "memory");
            if (e < epoch) __nanosleep(20);
        } while (e < epoch);
    }
    __syncthreads();
}

// ---------------- persistent chunk loop ---------------------------------------
__global__ void __launch_bounds__(256, 1)
chunk_loop(const float* __restrict__ alpha_t, const float* __restrict__ lr_t,
           const float* __restrict__ decay_t, const int* __restrict__ upd)
{
    if (*upd == 0) return;
    const float alpha = sigmoid_f(*alpha_t);
    const float lr    = sigmoid_f(*lr_t);
    const float decay = sigmoid_f(*decay_t);
    const float om    = 1.0f - alpha;
    const float escale = 2.0f / (float)(ROWS_CHUNK * D_IN);

    extern __shared__ char smem[];
    const uint32_t sbase = smem_u32(smem);
    unsigned epoch = 0;

    for (int c = 0; c < NCHUNK; c++) {
        const __half* Kch = g_Kh + (size_t)c * ROWS_CHUNK * D_IN;
        const float*  Vc  = g_V  + (size_t)c * ROWS_CHUNK * D_IN;
        __half* W2cur = (c & 1) ? g_W2hB : g_W2hA;
        __half* W2nxt = (c & 1) ? g_W2hA : g_W2hB;

        // P1: H = Kc @ W1 (f32), Ah = h(gelu(H))      128 tiles BM=64 K=512
        for (int t = blockIdx.x; t < 128; t += NB)
            tile_gemm<64,3,false,false,3>(Kch, D_IN, g_W1h, HID, D_IN,
                (t >> 3) * 64, (t & 7) * 128, sbase,
                g_H, g_Ah, HID, nullptr, 0.f, 0.f, 0.f, 0.f, nullptr);
        gsync(epoch);

        // P2: Eh = h((A @ W2 - Vc)*escale)            128 tiles BM=32 K=1024
        for (int t = blockIdx.x; t < 128; t += NB)
            tile_gemm<32,3,false,false,4>(g_Ah, HID, W2cur, D_IN, HID,
                (t >> 2) * 32, (t & 3) * 128, sbase,
                nullptr, g_Eh, D_IN, Vc, escale, 0.f, 0.f, 0.f, nullptr);
        gsync(epoch);

        // P3 (one wave, 128 tiles total):
        //   dHh = h((E @ W2^T)*gelu'(H))   64 tiles BM=128 K=512
        //   G2 = A^T @ E + fused W2/S2 update -> W2nxt   64 tiles BM=64 K=1024
        for (int t = blockIdx.x; t < 128; t += NB) {
            if (t < 64)
                tile_gemm<128,3,false,true,5>(g_Eh, D_IN, W2cur, D_IN, D_IN,
                    (t >> 3) * 128, (t & 7) * 128, sbase,
                    nullptr, g_dHh, HID, g_H, 0.f, 0.f, 0.f, 0.f, nullptr);
            else {
                int u = t - 64;
                tile_gemm<64,3,true,false,6>(g_Ah, HID, g_Eh, D_IN, ROWS_CHUNK,
                    (u >> 2) * 64, (u & 3) * 128, sbase,
                    g_W2, W2nxt, D_IN, nullptr, 0.f, decay, lr, om, g_S2);
            }
        }
        gsync(epoch);

        // P4: G1 = Kc^T @ dH, fused W1/S1 update      128 tiles BM=32 K=1024
        for (int t = blockIdx.x; t < 128; t += NB)
            tile_gemm<32,3,true,false,6>(Kch, D_IN, g_dHh, HID, ROWS_CHUNK,
                (t >> 3) * 32, (t & 7) * 128, sbase,
                g_W1, g_W1h, HID, nullptr, 0.f, decay, lr, om, g_S1);
        gsync(epoch);
    }
}

// ---------------- init / convert kernels -------------------------------------
__global__ void half_kernel(const float* __restrict__ src, __half* __restrict__ h, int n4) {
    int i = blockIdx.x * 256 + threadIdx.x;
    if (i >= n4) return;
    float4 v = ((const float4*)src)[i];
    ((uint2*)h)[i] = make_uint2(pack_h2(v.x, v.y), pack_h2(v.z, v.w));
}
__global__ void init_kernel(const float* __restrict__ w1, const float* __restrict__ w2) {
    int i = blockIdx.x * 256 + threadIdx.x;
    if (i < 8) g_grp[i * 32] = 0;
    if (i == 8) g_root = 0;
    if (i == 9) g_epochflag = 0;
    if (i < WSZ) {
        float a = w1[i], b = w2[i];
        g_W1[i] = a; g_W2[i] = b;
        g_S1[i] = 0.f; g_S2[i] = 0.f;
        g_W1h[i]  = __float2half_rn(a);
        g_W2hA[i] = __float2half_rn(b);
    }
}

// ---------------- launcher ----------------------------------------------------
extern "C" void kernel_launch(void* const* d_in, const int* in_sizes, int n_in,
                              void* d_out, int out_size)
{
    const float* x       = (const float*)d_in[0];
    const float* w_q     = (const float*)d_in[1];
    const float* w_k     = (const float*)d_in[2];
    const float* w_v     = (const float*)d_in[3];
    const float* mem_w1  = (const float*)d_in[4];
    const float* mem_w2  = (const float*)d_in[5];
    const float* alpha_t = (const float*)d_in[6];
    const float* lr_t    = (const float*)d_in[7];
    const float* decay_t = (const float*)d_in[8];
    const int*   upd     = (const int*)d_in[9];
    float* out = (float*)d_out;

    __half *xh, *wqh, *wkh, *wvh;
    cudaGetSymbolAddress((void**)&xh,  g_xh);
    cudaGetSymbolAddress((void**)&wqh, g_wqh);
    cudaGetSymbolAddress((void**)&wkh, g_wkh);
    cudaGetSymbolAddress((void**)&wvh, g_wvh);

    cudaFuncSetAttribute(qkv_kernel, cudaFuncAttributeMaxDynamicSharedMemorySize, P_SMEM_O);
    cudaFuncSetAttribute(ro1_kernel, cudaFuncAttributeMaxDynamicSharedMemorySize, P_SMEM_O);
    cudaFuncSetAttribute(ro2_kernel, cudaFuncAttributeMaxDynamicSharedMemorySize, P_SMEM_O);
    cudaFuncSetAttribute(chunk_loop, cudaFuncAttributeMaxDynamicSharedMemorySize, P_SMEM3);

    const dim3 thr(256);

    {
        int n4 = ROWS_TOTAL * D_IN / 4;
        half_kernel<<<(n4 + 255) / 256, thr>>>(x, xh, n4);
        int w4 = D_IN * D_IN / 4;
        half_kernel<<<(w4 + 255) / 256, thr>>>(w_q, wqh, w4);
        half_kernel<<<(w4 + 255) / 256, thr>>>(w_k, wkh, w4);
        half_kernel<<<(w4 + 255) / 256, thr>>>(w_v, wvh, w4);
    }
    init_kernel<<<WSZ / 256, thr>>>(mem_w1, mem_w2);

    qkv_kernel<<<dim3(D_IN / 128, ROWS_TOTAL / 128, 3), thr, P_SMEM_O>>>();

    chunk_loop<<<NB, thr, P_SMEM3>>>(alpha_t, lr_t, decay_t, upd);

    ro1_kernel<<<dim3(HID / 128, ROWS_TOTAL / 128), thr, P_SMEM_O>>>();
    ro2_kernel<<<dim3(D_IN / 128, ROWS_TOTAL / 128), thr, P_SMEM_O>>>(out);

    (void)in_sizes; (void)n_in; (void)out_size;
}

// round 13
// speedup vs baseline: 1.0972x; 1.0972x over previous
#include <cuda_runtime.h>
#include <cuda_fp16.h>
#include <cstdint>
#include <math.h>

// ---------------- problem constants ----------------------------------------
#define D_IN   512
#define HID    1024
#define SEQ    4096
#define BATCH  4
#define CHUNK  256
#define NCHUNK 16
#define ROWS_TOTAL (BATCH*SEQ)     // 16384
#define ROWS_CHUNK (BATCH*CHUNK)   // 1024
#define WSZ    (D_IN*HID)          // 524288
#define NBC    128                 // chunk-loop grid (divides all phase tile counts)

// ---------------- scratch (device globals) ----------------------------------
__device__ float g_V [ROWS_TOTAL*D_IN];   // chunk-major f32
__device__ float g_H [ROWS_CHUNK*HID];    // pre-gelu f32
__device__ float g_W1[WSZ], g_W2[WSZ], g_S1[WSZ], g_S2[WSZ];
__device__ unsigned g_arrive;

__device__ __half g_xh [ROWS_TOTAL*D_IN];
__device__ __half g_Qh [ROWS_TOTAL*D_IN];
__device__ __half g_Kh [ROWS_TOTAL*D_IN];        // chunk-major
__device__ __half g_W1h[WSZ];
__device__ __half g_W2hA[WSZ], g_W2hB[WSZ];      // hi ping-pong
__device__ __half g_Ah [ROWS_CHUNK*HID];
__device__ __half g_Eh [ROWS_CHUNK*D_IN];
__device__ __half g_dHh[ROWS_CHUNK*HID];
__device__ __half g_Hqh[ROWS_TOTAL*HID];
__device__ __half g_wqh[D_IN*D_IN], g_wkh[D_IN*D_IN], g_wvh[D_IN*D_IN];

// ---------------- math helpers ----------------------------------------------
__device__ __forceinline__ float gelu_f(float x) {
    return 0.5f * x * (1.0f + erff(x * 0.70710678118654752f));
}
__device__ __forceinline__ float gelu_grad_f(float x) {
    float cdf = 0.5f * (1.0f + erff(x * 0.70710678118654752f));
    float pdf = 0.3989422804014327f * __expf(-0.5f * x * x);
    return cdf + x * pdf;
}
__device__ __forceinline__ float sigmoid_f(float x) {
    return 1.0f / (1.0f + __expf(-x));
}
__device__ __forceinline__ uint32_t pack_h2(float v0, float v1) {
    __half2 hh = __floats2half2_rn(v0, v1);
    return *(uint32_t*)&hh;
}

// ---------------- PTX helpers ------------------------------------------------
__device__ __forceinline__ uint32_t smem_u32(const void* p) {
    uint32_t a;
    asm("{ .reg .u64 t; cvta.to.shared.u64 t, %1; cvt.u32.u64 %0, t; }" : "=r"(a) : "l"(p));
    return a;
}
__device__ __forceinline__ void cp16(uint32_t d, const void* s) {
    asm volatile("cp.async.cg.shared.global [%0], [%1], 16;" :: "r"(d), "l"(s));
}
__device__ __forceinline__ void ldsm4(uint32_t a, uint32_t& r0, uint32_t& r1,
                                      uint32_t& r2, uint32_t& r3) {
    asm volatile("ldmatrix.sync.aligned.m8n8.x4.shared.b16 {%0,%1,%2,%3}, [%4];"
                 : "=r"(r0), "=r"(r1), "=r"(r2), "=r"(r3) : "r"(a));
}
__device__ __forceinline__ void ldsm4t(uint32_t a, uint32_t& r0, uint32_t& r1,
                                       uint32_t& r2, uint32_t& r3) {
    asm volatile("ldmatrix.sync.aligned.m8n8.x4.trans.shared.b16 {%0,%1,%2,%3}, [%4];"
                 : "=r"(r0), "=r"(r1), "=r"(r2), "=r"(r3) : "r"(a));
}
__device__ __forceinline__ void mma16816(float* c, const uint32_t* a, const uint32_t* b) {
    asm volatile(
        "mma.sync.aligned.m16n8k16.row.col.f32.f16.f16.f32 "
        "{%0,%1,%2,%3}, {%4,%5,%6,%7}, {%8,%9}, {%0,%1,%2,%3};"
        : "+f"(c[0]), "+f"(c[1]), "+f"(c[2]), "+f"(c[3])
        : "r"(a[0]), "r"(a[1]), "r"(a[2]), "r"(a[3]), "r"(b[0]), "r"(b[1]));
}

#define P_SMEM 73728   // 3 stages * (A 8KB + B 16KB), BK=64, BM=64 case

// ============================================================================
// 1-term fp16 tile GEMM, BK=64, 3-stage cp.async pipeline. Tile BM x 128,
// 8 warps (2m x 4n), warp tile (BM/2) x 32.   [round-8 proven core]
// EPI: 0 C=v f32 | 1 Ch=h(v) | 3 C=v f32, Ch=h(gelu(v)) | 4 Ch=h((v-aux)*scale)
//      5 Ch=h(v*gelu'(aux)) | 6 momentum: s=decay*S-lr*v; S=s; w=om*C+s; C=w; Ch=h(w)
//      7 perm, Ch=h(v) | 8 perm, C=v f32 | 9 Ch=h(gelu(v))
// ============================================================================
template<int BM, bool TA, bool TB, int EPI>
__device__ __forceinline__ void tile_gemm(
    const __half* __restrict__ A_, int lda,
    const __half* __restrict__ B_, int ldb,
    int K, int m0, int n0, uint32_t sbase,
    float* __restrict__ C, __half* __restrict__ Ch, int ldc,
    const float* __restrict__ aux, float scale,
    float decay, float lr, float om, float* __restrict__ S)
{
    constexpr int A_T = BM * 128;        // BM x 64 halfs (bytes)
    constexpr int B_T = 16384;           // 128 x 64 halfs
    constexpr int BUF = A_T + B_T;
    constexpr int MT  = BM / 32;
    constexpr int ACP = (BM == 64) ? 2 : 1;   // A cp16 per thread

    const int tid = threadIdx.x, wid = tid >> 5, lane = tid & 31;
    const int wm = (wid & 1) * (BM / 2);
    const int wn = (wid >> 1) * 32;

    float acc[MT][4][4];
    #pragma unroll
    for (int a = 0; a < MT; a++)
        #pragma unroll
        for (int b = 0; b < 4; b++)
            #pragma unroll
            for (int d = 0; d < 4; d++) acc[a][b][d] = 0.f;

    // ---- A staging ----
    const __half* srcA[ACP];
    uint32_t dA[ACP];
    #pragma unroll
    for (int i = 0; i < ACP; i++) {
        int idx = tid + i * 256;
        if (!TA) {
            int r = idx >> 3, kq = idx & 7;                  // BM rows x 8 groups
            srcA[i] = A_ + (size_t)(m0 + r) * lda + kq * 8;
            dA[i] = r * 128 + ((kq ^ (r & 7)) << 4);
        } else {
            if (BM == 64) {
                int kr = idx >> 3, rq = idx & 7;             // 64 k-rows x 8 groups
                srcA[i] = A_ + (size_t)kr * lda + m0 + rq * 8;
                dA[i] = kr * 128 + ((rq ^ (kr & 7)) << 4);
            } else {
                int kr = idx >> 2, rq = idx & 3;             // 64 k-rows x 4 groups
                srcA[i] = A_ + (size_t)kr * lda + m0 + rq * 8;
                dA[i] = kr * 64 + ((rq ^ (kr & 3)) << 4);
            }
        }
    }
    const size_t advA = TA ? (size_t)64 * lda : 64;

    // ---- B staging (4 cp16 per thread) ----
    const __half* srcB[4];
    uint32_t dB[4];
    #pragma unroll
    for (int i = 0; i < 4; i++) {
        int fi = tid + i * 256;
        if (!TB) {
            int kr = fi >> 4, rq = fi & 15;                  // 64 k-rows x 16 groups
            srcB[i] = B_ + (size_t)kr * ldb + n0 + rq * 8;
            dB[i] = A_T + kr * 256 + ((rq ^ (kr & 7)) << 4);
        } else {
            int r = fi >> 3, kq = fi & 7;                    // 128 n-rows x 8 groups
            srcB[i] = B_ + (size_t)(n0 + r) * ldb + kq * 8;
            dB[i] = A_T + r * 128 + ((kq ^ (r & 7)) << 4);
        }
    }
    const size_t advB = TB ? 64 : (size_t)64 * ldb;

    // ---- ldmatrix addresses (s = 0..3 k16-steps within BK=64) ----
    uint32_t aA[4][MT], aB[4][2];
    #pragma unroll
    for (int s = 0; s < 4; s++) {
        #pragma unroll
        for (int mt = 0; mt < MT; mt++) {
            if (!TA) {
                int r = wm + mt * 16 + (lane & 15);
                int g = 2 * s + (lane >> 4);
                aA[s][mt] = r * 128 + ((g ^ (r & 7)) << 4);
            } else {
                int k = 16 * s + (lane & 7) + (lane >> 4) * 8;
                int mg = ((wm + mt * 16) >> 3) + ((lane >> 3) & 1);
                aA[s][mt] = (BM == 64) ? k * 128 + ((mg ^ (k & 7)) << 4)
                                       : k * 64  + ((mg ^ (k & 3)) << 4);
            }
        }
        #pragma unroll
        for (int j = 0; j < 2; j++) {
            if (!TB) {
                int k = 16 * s + (lane & 7) + ((lane >> 3) & 1) * 8;
                int ng = ((wn + j * 16) >> 3) + (lane >> 4);
                aB[s][j] = A_T + k * 256 + ((ng ^ (k & 7)) << 4);
            } else {
                int n = wn + j * 16 + (lane & 7) + (lane >> 4) * 8;
                int g = 2 * s + ((lane >> 3) & 1);
                aB[s][j] = A_T + n * 128 + ((g ^ (n & 7)) << 4);
            }
        }
    }

    const int NC = K >> 6;

    auto issue = [&](int c, int buf) {
        uint32_t b = sbase + buf * BUF;
        #pragma unroll
        for (int i = 0; i < ACP; i++) cp16(b + dA[i], srcA[i] + c * advA);
        #pragma unroll
        for (int i = 0; i < 4;   i++) cp16(b + dB[i], srcB[i] + c * advB);
        asm volatile("cp.async.commit_group;");
    };

    issue(0, 0);
    issue(1, 1);
    for (int c = 0; c < NC; c++) {
        if (c < NC - 1) asm volatile("cp.async.wait_group 1;");
        else            asm volatile("cp.async.wait_group 0;");
        __syncthreads();
        if (c + 2 < NC) issue(c + 2, (c + 2) % 3);

        const uint32_t bb = sbase + (c % 3) * BUF;
        uint32_t FA[4][MT][4], FB[4][4][2];
        #pragma unroll
        for (int s = 0; s < 4; s++) {
            #pragma unroll
            for (int mt = 0; mt < MT; mt++) {
                if (!TA) ldsm4 (bb + aA[s][mt], FA[s][mt][0], FA[s][mt][1], FA[s][mt][2], FA[s][mt][3]);
                else     ldsm4t(bb + aA[s][mt], FA[s][mt][0], FA[s][mt][1], FA[s][mt][2], FA[s][mt][3]);
            }
            #pragma unroll
            for (int j = 0; j < 2; j++) {
                if (!TB) ldsm4t(bb + aB[s][j], FB[s][2*j][0], FB[s][2*j][1], FB[s][2*j+1][0], FB[s][2*j+1][1]);
                else     ldsm4 (bb + aB[s][j], FB[s][2*j][0], FB[s][2*j][1], FB[s][2*j+1][0], FB[s][2*j+1][1]);
            }
        }
        #pragma unroll
        for (int s = 0; s < 4; s++)
            #pragma unroll
            for (int mt = 0; mt < MT; mt++)
                #pragma unroll
                for (int nt = 0; nt < 4; nt++)
                    mma16816(acc[mt][nt], FA[s][mt], FB[s][nt]);
    }
    __syncthreads();   // protect smem reuse by the caller's next tile

    // ---- epilogue ----
    #pragma unroll
    for (int mt = 0; mt < MT; mt++) {
        #pragma unroll
        for (int half = 0; half < 2; half++) {
            int r = m0 + wm + mt * 16 + (lane >> 2) + half * 8;
            #pragma unroll
            for (int nt = 0; nt < 4; nt++) {
                int cc = n0 + wn + nt * 8 + 2 * (lane & 3);
                float v0 = acc[mt][nt][half * 2 + 0];
                float v1 = acc[mt][nt][half * 2 + 1];
                size_t idx = (size_t)r * ldc + cc;
                if (EPI == 0) {
                    *(float2*)(C + idx) = make_float2(v0, v1);
                } else if (EPI == 1) {
                    *(uint32_t*)(Ch + idx) = pack_h2(v0, v1);
                } else if (EPI == 3) {
                    *(float2*)(C + idx) = make_float2(v0, v1);
                    *(uint32_t*)(Ch + idx) = pack_h2(gelu_f(v0), gelu_f(v1));
                } else if (EPI == 4) {
                    float2 a2 = *(const float2*)(aux + idx);
                    *(uint32_t*)(Ch + idx) = pack_h2((v0 - a2.x) * scale, (v1 - a2.y) * scale);
                } else if (EPI == 5) {
                    float2 a2 = *(const float2*)(aux + idx);
                    *(uint32_t*)(Ch + idx) = pack_h2(v0 * gelu_grad_f(a2.x), v1 * gelu_grad_f(a2.y));
                } else if (EPI == 6) {
                    float2 w = *(const float2*)(C + idx);
                    float2 s = *(const float2*)(S + idx);
                    float s0 = decay * s.x - lr * v0;
                    float s1 = decay * s.y - lr * v1;
                    float w0 = om * w.x + s0, w1 = om * w.y + s1;
                    *(float2*)(S + idx) = make_float2(s0, s1);
                    *(float2*)(C + idx) = make_float2(w0, w1);
                    *(uint32_t*)(Ch + idx) = pack_h2(w0, w1);
                } else if (EPI == 7) {
                    int b = r >> 12, sq = r & 4095, chn = sq >> 8, t = sq & 255;
                    size_t orow = (size_t)(chn * 1024 + b * 256 + t) * ldc + cc;
                    *(uint32_t*)(Ch + orow) = pack_h2(v0, v1);
                } else if (EPI == 8) {
                    int b = r >> 12, sq = r & 4095, chn = sq >> 8, t = sq & 255;
                    size_t orow = (size_t)(chn * 1024 + b * 256 + t) * ldc + cc;
                    *(float2*)(C + orow) = make_float2(v0, v1);
                } else { // EPI == 9
                    *(uint32_t*)(Ch + idx) = pack_h2(gelu_f(v0), gelu_f(v1));
                }
            }
        }
    }
}

// ---------------- standalone wrappers ---------------------------------------
__global__ void __launch_bounds__(256) qkv_kernel() {
    extern __shared__ char smem[];
    const uint32_t sbase = smem_u32(smem);
    int m0 = blockIdx.y * 64, n0 = blockIdx.x * 128;
    int z = blockIdx.z;
    if (z == 0)
        tile_gemm<64,false,false,1>(g_xh, D_IN, g_wqh, D_IN, D_IN,
            m0, n0, sbase, nullptr, g_Qh, D_IN, nullptr, 0.f, 0.f, 0.f, 0.f, nullptr);
    else if (z == 1)
        tile_gemm<64,false,false,7>(g_xh, D_IN, g_wkh, D_IN, D_IN,
            m0, n0, sbase, nullptr, g_Kh, D_IN, nullptr, 0.f, 0.f, 0.f, 0.f, nullptr);
    else
        tile_gemm<64,false,false,8>(g_xh, D_IN, g_wvh, D_IN, D_IN,
            m0, n0, sbase, g_V, nullptr, D_IN, nullptr, 0.f, 0.f, 0.f, 0.f, nullptr);
}

__global__ void __launch_bounds__(256) ro1_kernel() {
    extern __shared__ char smem[];
    const uint32_t sbase = smem_u32(smem);
    tile_gemm<64,false,false,9>(g_Qh, D_IN, g_W1h, HID, D_IN,
        blockIdx.y * 64, blockIdx.x * 128, sbase,
        nullptr, g_Hqh, HID, nullptr, 0.f, 0.f, 0.f, 0.f, nullptr);
}

__global__ void __launch_bounds__(256) ro2_kernel(float* __restrict__ out) {
    extern __shared__ char smem[];
    const uint32_t sbase = smem_u32(smem);
    tile_gemm<64,false,false,0>(g_Hqh, HID, g_W2hA, D_IN, HID,
        blockIdx.y * 64, blockIdx.x * 128, sbase,
        out, nullptr, D_IN, nullptr, 0.f, 0.f, 0.f, 0.f, nullptr);
}

// ---------------- software grid barrier (round-8 proven, NBC participants) ----
__device__ __forceinline__ void gsync(unsigned& epoch) {
    __syncthreads();
    if (threadIdx.x == 0) {
        __threadfence();
        epoch++;
        atomicAdd(&g_arrive, 1u);
        const unsigned target = epoch * NBC;
        while (__ldcg(&g_arrive) < target) __nanosleep(32);
        __threadfence();
    }
    __syncthreads();
}

// ---------------- persistent chunk loop --------------------------------------
__global__ void __launch_bounds__(256, 1)
chunk_loop(const float* __restrict__ alpha_t, const float* __restrict__ lr_t,
           const float* __restrict__ decay_t, const int* __restrict__ upd)
{
    if (*upd == 0) return;
    const float alpha = sigmoid_f(*alpha_t);
    const float lr    = sigmoid_f(*lr_t);
    const float decay = sigmoid_f(*decay_t);
    const float om    = 1.0f - alpha;
    const float escale = 2.0f / (float)(ROWS_CHUNK * D_IN);

    extern __shared__ char smem[];
    const uint32_t sbase = smem_u32(smem);
    unsigned epoch = 0;

    for (int c = 0; c < NCHUNK; c++) {
        const __half* Kch = g_Kh + (size_t)c * ROWS_CHUNK * D_IN;
        const float*  Vc  = g_V  + (size_t)c * ROWS_CHUNK * D_IN;
        __half* W2cur = (c & 1) ? g_W2hB : g_W2hA;
        __half* W2nxt = (c & 1) ? g_W2hA : g_W2hB;

        // P1: H = Kc @ W1 (f32), Ah = h(gelu(H))      128 tiles BM=64 K=512
        for (int t = blockIdx.x; t < 128; t += NBC)
            tile_gemm<64,false,false,3>(Kch, D_IN, g_W1h, HID, D_IN,
                (t >> 3) * 64, (t & 7) * 128, sbase,
                g_H, g_Ah, HID, nullptr, 0.f, 0.f, 0.f, 0.f, nullptr);
        gsync(epoch);

        // P2: Eh = h((A @ W2 - Vc)*escale)            128 tiles BM=32 K=1024
        for (int t = blockIdx.x; t < 128; t += NBC)
            tile_gemm<32,false,false,4>(g_Ah, HID, W2cur, D_IN, HID,
                (t >> 2) * 32, (t & 3) * 128, sbase,
                nullptr, g_Eh, D_IN, Vc, escale, 0.f, 0.f, 0.f, nullptr);
        gsync(epoch);

        // P3: dHh = h((E @ W2^T)*gelu'(H))            128 tiles BM=64 K=512
        //     G2 = A^T @ E, fused W2/S2 update -> W2nxt  128 tiles BM=32 K=1024
        for (int t = blockIdx.x; t < 256; t += NBC) {
            if (t < 128)
                tile_gemm<64,false,true,5>(g_Eh, D_IN, W2cur, D_IN, D_IN,
                    (t >> 3) * 64, (t & 7) * 128, sbase,
                    nullptr, g_dHh, HID, g_H, 0.f, 0.f, 0.f, 0.f, nullptr);
            else {
                int u = t - 128;
                tile_gemm<32,true,false,6>(g_Ah, HID, g_Eh, D_IN, ROWS_CHUNK,
                    (u >> 2) * 32, (u & 3) * 128, sbase,
                    g_W2, W2nxt, D_IN, nullptr, 0.f, decay, lr, om, g_S2);
            }
        }
        gsync(epoch);

        // P4: G1 = Kc^T @ dH, fused W1/S1 update      128 tiles BM=32 K=1024
        for (int t = blockIdx.x; t < 128; t += NBC)
            tile_gemm<32,true,false,6>(Kch, D_IN, g_dHh, HID, ROWS_CHUNK,
                (t >> 3) * 32, (t & 7) * 128, sbase,
                g_W1, g_W1h, HID, nullptr, 0.f, decay, lr, om, g_S1);
        gsync(epoch);
    }
}

// ---------------- init / convert kernels -------------------------------------
__global__ void half_kernel(const float* __restrict__ src, __half* __restrict__ h, int n4) {
    int i = blockIdx.x * 256 + threadIdx.x;
    if (i >= n4) return;
    float4 v = ((const float4*)src)[i];
    ((uint2*)h)[i] = make_uint2(pack_h2(v.x, v.y), pack_h2(v.z, v.w));
}
__global__ void init_kernel(const float* __restrict__ w1, const float* __restrict__ w2) {
    int i = blockIdx.x * 256 + threadIdx.x;
    if (i == 0) g_arrive = 0;
    if (i < WSZ) {
        float a = w1[i], b = w2[i];
        g_W1[i] = a; g_W2[i] = b;
        g_S1[i] = 0.f; g_S2[i] = 0.f;
        g_W1h[i]  = __float2half_rn(a);
        g_W2hA[i] = __float2half_rn(b);
    }
}

// ---------------- launcher ----------------------------------------------------
extern "C" void kernel_launch(void* const* d_in, const int* in_sizes, int n_in,
                              void* d_out, int out_size)
{
    const float* x       = (const float*)d_in[0];
    const float* w_q     = (const float*)d_in[1];
    const float* w_k     = (const float*)d_in[2];
    const float* w_v     = (const float*)d_in[3];
    const float* mem_w1  = (const float*)d_in[4];
    const float* mem_w2  = (const float*)d_in[5];
    const float* alpha_t = (const float*)d_in[6];
    const float* lr_t    = (const float*)d_in[7];
    const float* decay_t = (const float*)d_in[8];
    const int*   upd     = (const int*)d_in[9];
    float* out = (float*)d_out;

    __half *xh, *wqh, *wkh, *wvh;
    cudaGetSymbolAddress((void**)&xh,  g_xh);
    cudaGetSymbolAddress((void**)&wqh, g_wqh);
    cudaGetSymbolAddress((void**)&wkh, g_wkh);
    cudaGetSymbolAddress((void**)&wvh, g_wvh);

    cudaFuncSetAttribute(qkv_kernel, cudaFuncAttributeMaxDynamicSharedMemorySize, P_SMEM);
    cudaFuncSetAttribute(ro1_kernel, cudaFuncAttributeMaxDynamicSharedMemorySize, P_SMEM);
    cudaFuncSetAttribute(ro2_kernel, cudaFuncAttributeMaxDynamicSharedMemorySize, P_SMEM);
    cudaFuncSetAttribute(chunk_loop, cudaFuncAttributeMaxDynamicSharedMemorySize, P_SMEM);

    const dim3 thr(256);

    {
        int n4 = ROWS_TOTAL * D_IN / 4;
        half_kernel<<<(n4 + 255) / 256, thr>>>(x, xh, n4);
        int w4 = D_IN * D_IN / 4;
        half_kernel<<<(w4 + 255) / 256, thr>>>(w_q, wqh, w4);
        half_kernel<<<(w4 + 255) / 256, thr>>>(w_k, wkh, w4);
        half_kernel<<<(w4 + 255) / 256, thr>>>(w_v, wvh, w4);
    }
    init_kernel<<<WSZ / 256, thr>>>(mem_w1, mem_w2);

    qkv_kernel<<<dim3(D_IN / 128, ROWS_TOTAL / 64, 3), thr, P_SMEM>>>();

    chunk_loop<<<NBC, thr, P_SMEM>>>(alpha_t, lr_t, decay_t, upd);

    ro1_kernel<<<dim3(HID / 128, ROWS_TOTAL / 64), thr, P_SMEM>>>();
    ro2_kernel<<<dim3(D_IN / 128, ROWS_TOTAL / 64), thr, P_SMEM>>>(out);

    (void)in_sizes; (void)n_in; (void)out_size;
}

// round 14
// speedup vs baseline: 1.1283x; 1.0283x over previous
#include <cuda_runtime.h>
#include <cuda_fp16.h>
#include <cstdint>
#include <math.h>

// ---------------- problem constants ----------------------------------------
#define D_IN   512
#define HID    1024
#define SEQ    4096
#define BATCH  4
#define CHUNK  256
#define NCHUNK 16
#define ROWS_TOTAL (BATCH*SEQ)     // 16384
#define ROWS_CHUNK (BATCH*CHUNK)   // 1024
#define WSZ    (D_IN*HID)          // 524288
#define NB     148

// ---------------- scratch (device globals) ----------------------------------
__device__ float g_V [ROWS_TOTAL*D_IN];   // chunk-major f32
__device__ float g_H [ROWS_CHUNK*HID];    // pre-gelu f32
__device__ float g_W1[WSZ], g_W2[WSZ], g_S1[WSZ], g_S2[WSZ];
__device__ unsigned g_arrive;

__device__ __half g_xh [ROWS_TOTAL*D_IN];
__device__ __half g_Kh [ROWS_TOTAL*D_IN];        // chunk-major
__device__ __half g_W1h[WSZ];
__device__ __half g_W2hA[WSZ], g_W2hB[WSZ];      // hi ping-pong
__device__ __half g_M1h[WSZ];                    // wq @ W1_final
__device__ __half g_Ah [ROWS_CHUNK*HID];
__device__ __half g_Eh [ROWS_CHUNK*D_IN];
__device__ __half g_dHh[ROWS_CHUNK*HID];
__device__ __half g_Hqh[ROWS_TOTAL*HID];
__device__ __half g_wqh[D_IN*D_IN], g_wkh[D_IN*D_IN], g_wvh[D_IN*D_IN];

// ---------------- math helpers ----------------------------------------------
__device__ __forceinline__ float gelu_f(float x) {
    return 0.5f * x * (1.0f + erff(x * 0.70710678118654752f));
}
__device__ __forceinline__ float gelu_grad_f(float x) {
    float cdf = 0.5f * (1.0f + erff(x * 0.70710678118654752f));
    float pdf = 0.3989422804014327f * __expf(-0.5f * x * x);
    return cdf + x * pdf;
}
__device__ __forceinline__ float sigmoid_f(float x) {
    return 1.0f / (1.0f + __expf(-x));
}
__device__ __forceinline__ uint32_t pack_h2(float v0, float v1) {
    __half2 hh = __floats2half2_rn(v0, v1);
    return *(uint32_t*)&hh;
}

// ---------------- PTX helpers ------------------------------------------------
__device__ __forceinline__ uint32_t smem_u32(const void* p) {
    uint32_t a;
    asm("{ .reg .u64 t; cvta.to.shared.u64 t, %1; cvt.u32.u64 %0, t; }" : "=r"(a) : "l"(p));
    return a;
}
__device__ __forceinline__ void cp16(uint32_t d, const void* s) {
    asm volatile("cp.async.cg.shared.global [%0], [%1], 16;" :: "r"(d), "l"(s));
}
__device__ __forceinline__ void ldsm4(uint32_t a, uint32_t& r0, uint32_t& r1,
                                      uint32_t& r2, uint32_t& r3) {
    asm volatile("ldmatrix.sync.aligned.m8n8.x4.shared.b16 {%0,%1,%2,%3}, [%4];"
                 : "=r"(r0), "=r"(r1), "=r"(r2), "=r"(r3) : "r"(a));
}
__device__ __forceinline__ void ldsm4t(uint32_t a, uint32_t& r0, uint32_t& r1,
                                       uint32_t& r2, uint32_t& r3) {
    asm volatile("ldmatrix.sync.aligned.m8n8.x4.trans.shared.b16 {%0,%1,%2,%3}, [%4];"
                 : "=r"(r0), "=r"(r1), "=r"(r2), "=r"(r3) : "r"(a));
}
__device__ __forceinline__ void mma16816(float* c, const uint32_t* a, const uint32_t* b) {
    asm volatile(
        "mma.sync.aligned.m16n8k16.row.col.f32.f16.f16.f32 "
        "{%0,%1,%2,%3}, {%4,%5,%6,%7}, {%8,%9}, {%0,%1,%2,%3};"
        : "+f"(c[0]), "+f"(c[1]), "+f"(c[2]), "+f"(c[3])
        : "r"(a[0]), "r"(a[1]), "r"(a[2]), "r"(a[3]), "r"(b[0]), "r"(b[1]));
}

#define P_SMEM 73728   // 3 stages * (A 8KB + B 16KB), BK=64, BM=64 case

// ============================================================================
// 1-term fp16 tile GEMM, BK=64, 3-stage cp.async pipeline. Tile BM x 128,
// 8 warps (2m x 4n), warp tile (BM/2) x 32.   [round-8 proven core]
// EPI: 0 C=v f32 | 1 Ch=h(v) | 3 C=v f32, Ch=h(gelu(v)) | 4 Ch=h((v-aux)*scale)
//      5 Ch=h(v*gelu'(aux)) | 6 momentum: s=decay*S-lr*v; S=s; w=om*C+s; C=w; Ch=h(w)
//      7 perm, Ch=h(v) | 8 perm, C=v f32 | 9 Ch=h(gelu(v))
// ============================================================================
template<int BM, bool TA, bool TB, int EPI>
__device__ __forceinline__ void tile_gemm(
    const __half* __restrict__ A_, int lda,
    const __half* __restrict__ B_, int ldb,
    int K, int m0, int n0, uint32_t sbase,
    float* __restrict__ C, __half* __restrict__ Ch, int ldc,
    const float* __restrict__ aux, float scale,
    float decay, float lr, float om, float* __restrict__ S)
{
    constexpr int A_T = BM * 128;        // BM x 64 halfs (bytes)
    constexpr int B_T = 16384;           // 128 x 64 halfs
    constexpr int BUF = A_T + B_T;
    constexpr int MT  = BM / 32;
    constexpr int ACP = (BM == 64) ? 2 : 1;   // A cp16 per thread

    const int tid = threadIdx.x, wid = tid >> 5, lane = tid & 31;
    const int wm = (wid & 1) * (BM / 2);
    const int wn = (wid >> 1) * 32;

    float acc[MT][4][4];
    #pragma unroll
    for (int a = 0; a < MT; a++)
        #pragma unroll
        for (int b = 0; b < 4; b++)
            #pragma unroll
            for (int d = 0; d < 4; d++) acc[a][b][d] = 0.f;

    // ---- A staging ----
    const __half* srcA[ACP];
    uint32_t dA[ACP];
    #pragma unroll
    for (int i = 0; i < ACP; i++) {
        int idx = tid + i * 256;
        if (!TA) {
            int r = idx >> 3, kq = idx & 7;                  // BM rows x 8 groups
            srcA[i] = A_ + (size_t)(m0 + r) * lda + kq * 8;
            dA[i] = r * 128 + ((kq ^ (r & 7)) << 4);
        } else {
            if (BM == 64) {
                int kr = idx >> 3, rq = idx & 7;             // 64 k-rows x 8 groups
                srcA[i] = A_ + (size_t)kr * lda + m0 + rq * 8;
                dA[i] = kr * 128 + ((rq ^ (kr & 7)) << 4);
            } else {
                int kr = idx >> 2, rq = idx & 3;             // 64 k-rows x 4 groups
                srcA[i] = A_ + (size_t)kr * lda + m0 + rq * 8;
                dA[i] = kr * 64 + ((rq ^ (kr & 3)) << 4);
            }
        }
    }
    const size_t advA = TA ? (size_t)64 * lda : 64;

    // ---- B staging (4 cp16 per thread) ----
    const __half* srcB[4];
    uint32_t dB[4];
    #pragma unroll
    for (int i = 0; i < 4; i++) {
        int fi = tid + i * 256;
        if (!TB) {
            int kr = fi >> 4, rq = fi & 15;                  // 64 k-rows x 16 groups
            srcB[i] = B_ + (size_t)kr * ldb + n0 + rq * 8;
            dB[i] = A_T + kr * 256 + ((rq ^ (kr & 7)) << 4);
        } else {
            int r = fi >> 3, kq = fi & 7;                    // 128 n-rows x 8 groups
            srcB[i] = B_ + (size_t)(n0 + r) * ldb + kq * 8;
            dB[i] = A_T + r * 128 + ((kq ^ (r & 7)) << 4);
        }
    }
    const size_t advB = TB ? 64 : (size_t)64 * ldb;

    // ---- ldmatrix addresses (s = 0..3 k16-steps within BK=64) ----
    uint32_t aA[4][MT], aB[4][2];
    #pragma unroll
    for (int s = 0; s < 4; s++) {
        #pragma unroll
        for (int mt = 0; mt < MT; mt++) {
            if (!TA) {
                int r = wm + mt * 16 + (lane & 15);
                int g = 2 * s + (lane >> 4);
                aA[s][mt] = r * 128 + ((g ^ (r & 7)) << 4);
            } else {
                int k = 16 * s + (lane & 7) + (lane >> 4) * 8;
                int mg = ((wm + mt * 16) >> 3) + ((lane >> 3) & 1);
                aA[s][mt] = (BM == 64) ? k * 128 + ((mg ^ (k & 7)) << 4)
                                       : k * 64  + ((mg ^ (k & 3)) << 4);
            }
        }
        #pragma unroll
        for (int j = 0; j < 2; j++) {
            if (!TB) {
                int k = 16 * s + (lane & 7) + ((lane >> 3) & 1) * 8;
                int ng = ((wn + j * 16) >> 3) + (lane >> 4);
                aB[s][j] = A_T + k * 256 + ((ng ^ (k & 7)) << 4);
            } else {
                int n = wn + j * 16 + (lane & 7) + (lane >> 4) * 8;
                int g = 2 * s + ((lane >> 3) & 1);
                aB[s][j] = A_T + n * 128 + ((g ^ (n & 7)) << 4);
            }
        }
    }

    const int NC = K >> 6;

    auto issue = [&](int c, int buf) {
        uint32_t b = sbase + buf * BUF;
        #pragma unroll
        for (int i = 0; i < ACP; i++) cp16(b + dA[i], srcA[i] + c * advA);
        #pragma unroll
        for (int i = 0; i < 4;   i++) cp16(b + dB[i], srcB[i] + c * advB);
        asm volatile("cp.async.commit_group;");
    };

    issue(0, 0);
    issue(1, 1);
    for (int c = 0; c < NC; c++) {
        if (c < NC - 1) asm volatile("cp.async.wait_group 1;");
        else            asm volatile("cp.async.wait_group 0;");
        __syncthreads();
        if (c + 2 < NC) issue(c + 2, (c + 2) % 3);

        const uint32_t bb = sbase + (c % 3) * BUF;
        uint32_t FA[4][MT][4], FB[4][4][2];
        #pragma unroll
        for (int s = 0; s < 4; s++) {
            #pragma unroll
            for (int mt = 0; mt < MT; mt++) {
                if (!TA) ldsm4 (bb + aA[s][mt], FA[s][mt][0], FA[s][mt][1], FA[s][mt][2], FA[s][mt][3]);
                else     ldsm4t(bb + aA[s][mt], FA[s][mt][0], FA[s][mt][1], FA[s][mt][2], FA[s][mt][3]);
            }
            #pragma unroll
            for (int j = 0; j < 2; j++) {
                if (!TB) ldsm4t(bb + aB[s][j], FB[s][2*j][0], FB[s][2*j][1], FB[s][2*j+1][0], FB[s][2*j+1][1]);
                else     ldsm4 (bb + aB[s][j], FB[s][2*j][0], FB[s][2*j][1], FB[s][2*j+1][0], FB[s][2*j+1][1]);
            }
        }
        #pragma unroll
        for (int s = 0; s < 4; s++)
            #pragma unroll
            for (int mt = 0; mt < MT; mt++)
                #pragma unroll
                for (int nt = 0; nt < 4; nt++)
                    mma16816(acc[mt][nt], FA[s][mt], FB[s][nt]);
    }
    __syncthreads();   // protect smem reuse by the caller's next tile

    // ---- epilogue ----
    #pragma unroll
    for (int mt = 0; mt < MT; mt++) {
        #pragma unroll
        for (int half = 0; half < 2; half++) {
            int r = m0 + wm + mt * 16 + (lane >> 2) + half * 8;
            #pragma unroll
            for (int nt = 0; nt < 4; nt++) {
                int cc = n0 + wn + nt * 8 + 2 * (lane & 3);
                float v0 = acc[mt][nt][half * 2 + 0];
                float v1 = acc[mt][nt][half * 2 + 1];
                size_t idx = (size_t)r * ldc + cc;
                if (EPI == 0) {
                    *(float2*)(C + idx) = make_float2(v0, v1);
                } else if (EPI == 1) {
                    *(uint32_t*)(Ch + idx) = pack_h2(v0, v1);
                } else if (EPI == 3) {
                    *(float2*)(C + idx) = make_float2(v0, v1);
                    *(uint32_t*)(Ch + idx) = pack_h2(gelu_f(v0), gelu_f(v1));
                } else if (EPI == 4) {
                    float2 a2 = *(const float2*)(aux + idx);
                    *(uint32_t*)(Ch + idx) = pack_h2((v0 - a2.x) * scale, (v1 - a2.y) * scale);
                } else if (EPI == 5) {
                    float2 a2 = *(const float2*)(aux + idx);
                    *(uint32_t*)(Ch + idx) = pack_h2(v0 * gelu_grad_f(a2.x), v1 * gelu_grad_f(a2.y));
                } else if (EPI == 6) {
                    float2 w = *(const float2*)(C + idx);
                    float2 s = *(const float2*)(S + idx);
                    float s0 = decay * s.x - lr * v0;
                    float s1 = decay * s.y - lr * v1;
                    float w0 = om * w.x + s0, w1 = om * w.y + s1;
                    *(float2*)(S + idx) = make_float2(s0, s1);
                    *(float2*)(C + idx) = make_float2(w0, w1);
                    *(uint32_t*)(Ch + idx) = pack_h2(w0, w1);
                } else if (EPI == 7) {
                    int b = r >> 12, sq = r & 4095, chn = sq >> 8, t = sq & 255;
                    size_t orow = (size_t)(chn * 1024 + b * 256 + t) * ldc + cc;
                    *(uint32_t*)(Ch + orow) = pack_h2(v0, v1);
                } else if (EPI == 8) {
                    int b = r >> 12, sq = r & 4095, chn = sq >> 8, t = sq & 255;
                    size_t orow = (size_t)(chn * 1024 + b * 256 + t) * ldc + cc;
                    *(float2*)(C + orow) = make_float2(v0, v1);
                } else { // EPI == 9
                    *(uint32_t*)(Ch + idx) = pack_h2(gelu_f(v0), gelu_f(v1));
                }
            }
        }
    }
}

// ---------------- standalone wrappers ---------------------------------------
// KV only (Q projection eliminated via M1 = wq @ W1_final)
__global__ void __launch_bounds__(256) kv_kernel() {
    extern __shared__ char smem[];
    const uint32_t sbase = smem_u32(smem);
    int m0 = blockIdx.y * 64, n0 = blockIdx.x * 128;
    if (blockIdx.z == 0)
        tile_gemm<64,false,false,7>(g_xh, D_IN, g_wkh, D_IN, D_IN,
            m0, n0, sbase, nullptr, g_Kh, D_IN, nullptr, 0.f, 0.f, 0.f, 0.f, nullptr);
    else
        tile_gemm<64,false,false,8>(g_xh, D_IN, g_wvh, D_IN, D_IN,
            m0, n0, sbase, g_V, nullptr, D_IN, nullptr, 0.f, 0.f, 0.f, 0.f, nullptr);
}

// M1 = wq @ W1_final  (tiny: [512 x 1024], K=512, 64 tiles)
__global__ void __launch_bounds__(256) m1_kernel() {
    extern __shared__ char smem[];
    const uint32_t sbase = smem_u32(smem);
    tile_gemm<64,false,false,1>(g_wqh, D_IN, g_W1h, HID, D_IN,
        blockIdx.y * 64, blockIdx.x * 128, sbase,
        nullptr, g_M1h, HID, nullptr, 0.f, 0.f, 0.f, 0.f, nullptr);
}

// Hq = gelu(x @ M1)
__global__ void __launch_bounds__(256) ro1_kernel() {
    extern __shared__ char smem[];
    const uint32_t sbase = smem_u32(smem);
    tile_gemm<64,false,false,9>(g_xh, D_IN, g_M1h, HID, D_IN,
        blockIdx.y * 64, blockIdx.x * 128, sbase,
        nullptr, g_Hqh, HID, nullptr, 0.f, 0.f, 0.f, 0.f, nullptr);
}

__global__ void __launch_bounds__(256) ro2_kernel(float* __restrict__ out) {
    extern __shared__ char smem[];
    const uint32_t sbase = smem_u32(smem);
    tile_gemm<64,false,false,0>(g_Hqh, HID, g_W2hA, D_IN, HID,
        blockIdx.y * 64, blockIdx.x * 128, sbase,
        out, nullptr, D_IN, nullptr, 0.f, 0.f, 0.f, 0.f, nullptr);
}

// ---------------- software grid barrier (round-8 proven) ----------------------
__device__ __forceinline__ void gsync(unsigned& epoch) {
    __syncthreads();
    if (threadIdx.x == 0) {
        __threadfence();
        epoch++;
        atomicAdd(&g_arrive, 1u);
        const unsigned target = epoch * NB;
        while (__ldcg(&g_arrive) < target) __nanosleep(32);
        __threadfence();
    }
    __syncthreads();
}

// ---------------- persistent chunk loop --------------------------------------
__global__ void __launch_bounds__(256, 1)
chunk_loop(const float* __restrict__ alpha_t, const float* __restrict__ lr_t,
           const float* __restrict__ decay_t, const int* __restrict__ upd)
{
    if (*upd == 0) return;
    const float alpha = sigmoid_f(*alpha_t);
    const float lr    = sigmoid_f(*lr_t);
    const float decay = sigmoid_f(*decay_t);
    const float om    = 1.0f - alpha;
    const float escale = 2.0f / (float)(ROWS_CHUNK * D_IN);

    extern __shared__ char smem[];
    const uint32_t sbase = smem_u32(smem);
    unsigned epoch = 0;

    for (int c = 0; c < NCHUNK; c++) {
        const __half* Kch = g_Kh + (size_t)c * ROWS_CHUNK * D_IN;
        const float*  Vc  = g_V  + (size_t)c * ROWS_CHUNK * D_IN;
        __half* W2cur = (c & 1) ? g_W2hB : g_W2hA;
        __half* W2nxt = (c & 1) ? g_W2hA : g_W2hB;

        // P1: H = Kc @ W1 (f32), Ah = h(gelu(H))      128 tiles BM=64 K=512
        for (int t = blockIdx.x; t < 128; t += NB)
            tile_gemm<64,false,false,3>(Kch, D_IN, g_W1h, HID, D_IN,
                (t >> 3) * 64, (t & 7) * 128, sbase,
                g_H, g_Ah, HID, nullptr, 0.f, 0.f, 0.f, 0.f, nullptr);
        gsync(epoch);

        // P2: Eh = h((A @ W2 - Vc)*escale)            128 tiles BM=32 K=1024
        for (int t = blockIdx.x; t < 128; t += NB)
            tile_gemm<32,false,false,4>(g_Ah, HID, W2cur, D_IN, HID,
                (t >> 2) * 32, (t & 3) * 128, sbase,
                nullptr, g_Eh, D_IN, Vc, escale, 0.f, 0.f, 0.f, nullptr);
        gsync(epoch);

        // P3: dHh = h((E @ W2^T)*gelu'(H))            128 tiles BM=64 K=512
        //     G2 = A^T @ E, fused W2/S2 update -> W2nxt  128 tiles BM=32 K=1024
        for (int t = blockIdx.x; t < 256; t += NB) {
            if (t < 128)
                tile_gemm<64,false,true,5>(g_Eh, D_IN, W2cur, D_IN, D_IN,
                    (t >> 3) * 64, (t & 7) * 128, sbase,
                    nullptr, g_dHh, HID, g_H, 0.f, 0.f, 0.f, 0.f, nullptr);
            else {
                int u = t - 128;
                tile_gemm<32,true,false,6>(g_Ah, HID, g_Eh, D_IN, ROWS_CHUNK,
                    (u >> 2) * 32, (u & 3) * 128, sbase,
                    g_W2, W2nxt, D_IN, nullptr, 0.f, decay, lr, om, g_S2);
            }
        }
        gsync(epoch);

        // P4: G1 = Kc^T @ dH, fused W1/S1 update      128 tiles BM=32 K=1024
        for (int t = blockIdx.x; t < 128; t += NB)
            tile_gemm<32,true,false,6>(Kch, D_IN, g_dHh, HID, ROWS_CHUNK,
                (t >> 3) * 32, (t & 7) * 128, sbase,
                g_W1, g_W1h, HID, nullptr, 0.f, decay, lr, om, g_S1);
        gsync(epoch);
    }
}

// ---------------- init / convert kernels -------------------------------------
__global__ void half_kernel(const float* __restrict__ src, __half* __restrict__ h, int n4) {
    int i = blockIdx.x * 256 + threadIdx.x;
    if (i >= n4) return;
    float4 v = ((const float4*)src)[i];
    ((uint2*)h)[i] = make_uint2(pack_h2(v.x, v.y), pack_h2(v.z, v.w));
}
__global__ void init_kernel(const float* __restrict__ w1, const float* __restrict__ w2) {
    int i = blockIdx.x * 256 + threadIdx.x;
    if (i == 0) g_arrive = 0;
    if (i < WSZ) {
        float a = w1[i], b = w2[i];
        g_W1[i] = a; g_W2[i] = b;
        g_S1[i] = 0.f; g_S2[i] = 0.f;
        g_W1h[i]  = __float2half_rn(a);
        g_W2hA[i] = __float2half_rn(b);
    }
}

// ---------------- launcher ----------------------------------------------------
extern "C" void kernel_launch(void* const* d_in, const int* in_sizes, int n_in,
                              void* d_out, int out_size)
{
    const float* x       = (const float*)d_in[0];
    const float* w_q     = (const float*)d_in[1];
    const float* w_k     = (const float*)d_in[2];
    const float* w_v     = (const float*)d_in[3];
    const float* mem_w1  = (const float*)d_in[4];
    const float* mem_w2  = (const float*)d_in[5];
    const float* alpha_t = (const float*)d_in[6];
    const float* lr_t    = (const float*)d_in[7];
    const float* decay_t = (const float*)d_in[8];
    const int*   upd     = (const int*)d_in[9];
    float* out = (float*)d_out;

    __half *xh, *wqh, *wkh, *wvh;
    cudaGetSymbolAddress((void**)&xh,  g_xh);
    cudaGetSymbolAddress((void**)&wqh, g_wqh);
    cudaGetSymbolAddress((void**)&wkh, g_wkh);
    cudaGetSymbolAddress((void**)&wvh, g_wvh);

    cudaFuncSetAttribute(kv_kernel,  cudaFuncAttributeMaxDynamicSharedMemorySize, P_SMEM);
    cudaFuncSetAttribute(m1_kernel,  cudaFuncAttributeMaxDynamicSharedMemorySize, P_SMEM);
    cudaFuncSetAttribute(ro1_kernel, cudaFuncAttributeMaxDynamicSharedMemorySize, P_SMEM);
    cudaFuncSetAttribute(ro2_kernel, cudaFuncAttributeMaxDynamicSharedMemorySize, P_SMEM);
    cudaFuncSetAttribute(chunk_loop, cudaFuncAttributeMaxDynamicSharedMemorySize, P_SMEM);

    const dim3 thr(256);

    {
        int n4 = ROWS_TOTAL * D_IN / 4;
        half_kernel<<<(n4 + 255) / 256, thr>>>(x, xh, n4);
        int w4 = D_IN * D_IN / 4;
        half_kernel<<<(w4 + 255) / 256, thr>>>(w_q, wqh, w4);
        half_kernel<<<(w4 + 255) / 256, thr>>>(w_k, wkh, w4);
        half_kernel<<<(w4 + 255) / 256, thr>>>(w_v, wvh, w4);
    }
    init_kernel<<<WSZ / 256, thr>>>(mem_w1, mem_w2);

    // K, V projections only (chunk-major permuted stores)
    kv_kernel<<<dim3(D_IN / 128, ROWS_TOTAL / 64, 2), thr, P_SMEM>>>();

    // 16-chunk memory update loop: one persistent kernel
    chunk_loop<<<NB, thr, P_SMEM>>>(alpha_t, lr_t, decay_t, upd);

    // Readout: M1 = wq @ W1_final; Hq = gelu(x @ M1); out = Hq @ W2_final
    m1_kernel<<<dim3(HID / 128, D_IN / 64), thr, P_SMEM>>>();
    ro1_kernel<<<dim3(HID / 128, ROWS_TOTAL / 64), thr, P_SMEM>>>();
    ro2_kernel<<<dim3(D_IN / 128, ROWS_TOTAL / 64), thr, P_SMEM>>>(out);

    (void)in_sizes; (void)n_in; (void)out_size;
}

// round 15
// speedup vs baseline: 1.1417x; 1.0119x over previous
#include <cuda_runtime.h>
#include <cuda_fp16.h>
#include <cstdint>
#include <math.h>

// ---------------- problem constants ----------------------------------------
#define D_IN   512
#define HID    1024
#define SEQ    4096
#define BATCH  4
#define CHUNK  256
#define NCHUNK 16
#define ROWS_TOTAL (BATCH*SEQ)     // 16384
#define ROWS_CHUNK (BATCH*CHUNK)   // 1024
#define WSZ    (D_IN*HID)          // 524288
#define NB     148

// ---------------- scratch (device globals) ----------------------------------
__device__ float g_V [ROWS_TOTAL*D_IN];   // chunk-major f32
__device__ float g_H [ROWS_CHUNK*HID];    // pre-gelu f32
__device__ float g_W1[WSZ], g_W2[WSZ], g_S1[WSZ], g_S2[WSZ];
__device__ unsigned g_arrive;

__device__ __half g_xh [ROWS_TOTAL*D_IN];
__device__ __half g_Kh [ROWS_TOTAL*D_IN];        // chunk-major
__device__ __half g_W1h[WSZ];
__device__ __half g_W2hA[WSZ], g_W2hB[WSZ];      // hi ping-pong
__device__ __half g_M1h[WSZ];                    // wq @ W1_final
__device__ __half g_Ah [ROWS_CHUNK*HID];
__device__ __half g_Eh [ROWS_CHUNK*D_IN];
__device__ __half g_dHh[ROWS_CHUNK*HID];
__device__ __half g_Hqh[ROWS_TOTAL*HID];
__device__ __half g_wqh[D_IN*D_IN], g_wkh[D_IN*D_IN], g_wvh[D_IN*D_IN];

// ---------------- math helpers ----------------------------------------------
__device__ __forceinline__ float gelu_f(float x) {
    return 0.5f * x * (1.0f + erff(x * 0.70710678118654752f));
}
__device__ __forceinline__ float gelu_grad_f(float x) {
    float cdf = 0.5f * (1.0f + erff(x * 0.70710678118654752f));
    float pdf = 0.3989422804014327f * __expf(-0.5f * x * x);
    return cdf + x * pdf;
}
__device__ __forceinline__ float sigmoid_f(float x) {
    return 1.0f / (1.0f + __expf(-x));
}
__device__ __forceinline__ uint32_t pack_h2(float v0, float v1) {
    __half2 hh = __floats2half2_rn(v0, v1);
    return *(uint32_t*)&hh;
}

// ---------------- PTX helpers ------------------------------------------------
__device__ __forceinline__ uint32_t smem_u32(const void* p) {
    uint32_t a;
    asm("{ .reg .u64 t; cvta.to.shared.u64 t, %1; cvt.u32.u64 %0, t; }" : "=r"(a) : "l"(p));
    return a;
}
__device__ __forceinline__ void cp16(uint32_t d, const void* s) {
    asm volatile("cp.async.cg.shared.global [%0], [%1], 16;" :: "r"(d), "l"(s));
}
__device__ __forceinline__ void pref_l2(const void* p) {
    asm volatile("prefetch.global.L2 [%0];" :: "l"(p));
}
__device__ __forceinline__ void ldsm4(uint32_t a, uint32_t& r0, uint32_t& r1,
                                      uint32_t& r2, uint32_t& r3) {
    asm volatile("ldmatrix.sync.aligned.m8n8.x4.shared.b16 {%0,%1,%2,%3}, [%4];"
                 : "=r"(r0), "=r"(r1), "=r"(r2), "=r"(r3) : "r"(a));
}
__device__ __forceinline__ void ldsm4t(uint32_t a, uint32_t& r0, uint32_t& r1,
                                       uint32_t& r2, uint32_t& r3) {
    asm volatile("ldmatrix.sync.aligned.m8n8.x4.trans.shared.b16 {%0,%1,%2,%3}, [%4];"
                 : "=r"(r0), "=r"(r1), "=r"(r2), "=r"(r3) : "r"(a));
}
__device__ __forceinline__ void mma16816(float* c, const uint32_t* a, const uint32_t* b) {
    asm volatile(
        "mma.sync.aligned.m16n8k16.row.col.f32.f16.f16.f32 "
        "{%0,%1,%2,%3}, {%4,%5,%6,%7}, {%8,%9}, {%0,%1,%2,%3};"
        : "+f"(c[0]), "+f"(c[1]), "+f"(c[2]), "+f"(c[3])
        : "r"(a[0]), "r"(a[1]), "r"(a[2]), "r"(a[3]), "r"(b[0]), "r"(b[1]));
}

#define P_SMEM 73728   // 3 stages * (A 8KB + B 16KB), BK=64, BM=64 case

// ============================================================================
// 1-term fp16 tile GEMM, BK=64, 3-stage cp.async pipeline. Tile BM x 128,
// 8 warps (2m x 4n), warp tile (BM/2) x 32.   [round-8 proven core]
// EPI: 0 C=v f32 | 1 Ch=h(v) | 3 C=v f32, Ch=h(gelu(v)) | 4 Ch=h((v-aux)*scale)
//      5 Ch=h(v*gelu'(aux)) | 6 momentum: s=decay*S-lr*v; S=s; w=om*C+s; C=w; Ch=h(w)
//      7 perm, Ch=h(v) | 8 perm, C=v f32 | 9 Ch=h(gelu(v))
// ============================================================================
template<int BM, bool TA, bool TB, int EPI>
__device__ __forceinline__ void tile_gemm(
    const __half* __restrict__ A_, int lda,
    const __half* __restrict__ B_, int ldb,
    int K, int m0, int n0, uint32_t sbase,
    float* __restrict__ C, __half* __restrict__ Ch, int ldc,
    const float* __restrict__ aux, float scale,
    float decay, float lr, float om, float* __restrict__ S)
{
    constexpr int A_T = BM * 128;
    constexpr int B_T = 16384;
    constexpr int BUF = A_T + B_T;
    constexpr int MT  = BM / 32;
    constexpr int ACP = (BM == 64) ? 2 : 1;

    const int tid = threadIdx.x, wid = tid >> 5, lane = tid & 31;
    const int wm = (wid & 1) * (BM / 2);
    const int wn = (wid >> 1) * 32;

    float acc[MT][4][4];
    #pragma unroll
    for (int a = 0; a < MT; a++)
        #pragma unroll
        for (int b = 0; b < 4; b++)
            #pragma unroll
            for (int d = 0; d < 4; d++) acc[a][b][d] = 0.f;

    const __half* srcA[ACP];
    uint32_t dA[ACP];
    #pragma unroll
    for (int i = 0; i < ACP; i++) {
        int idx = tid + i * 256;
        if (!TA) {
            int r = idx >> 3, kq = idx & 7;
            srcA[i] = A_ + (size_t)(m0 + r) * lda + kq * 8;
            dA[i] = r * 128 + ((kq ^ (r & 7)) << 4);
        } else {
            if (BM == 64) {
                int kr = idx >> 3, rq = idx & 7;
                srcA[i] = A_ + (size_t)kr * lda + m0 + rq * 8;
                dA[i] = kr * 128 + ((rq ^ (kr & 7)) << 4);
            } else {
                int kr = idx >> 2, rq = idx & 3;
                srcA[i] = A_ + (size_t)kr * lda + m0 + rq * 8;
                dA[i] = kr * 64 + ((rq ^ (kr & 3)) << 4);
            }
        }
    }
    const size_t advA = TA ? (size_t)64 * lda : 64;

    const __half* srcB[4];
    uint32_t dB[4];
    #pragma unroll
    for (int i = 0; i < 4; i++) {
        int fi = tid + i * 256;
        if (!TB) {
            int kr = fi >> 4, rq = fi & 15;
            srcB[i] = B_ + (size_t)kr * ldb + n0 + rq * 8;
            dB[i] = A_T + kr * 256 + ((rq ^ (kr & 7)) << 4);
        } else {
            int r = fi >> 3, kq = fi & 7;
            srcB[i] = B_ + (size_t)(n0 + r) * ldb + kq * 8;
            dB[i] = A_T + r * 128 + ((kq ^ (r & 7)) << 4);
        }
    }
    const size_t advB = TB ? 64 : (size_t)64 * ldb;

    uint32_t aA[4][MT], aB[4][2];
    #pragma unroll
    for (int s = 0; s < 4; s++) {
        #pragma unroll
        for (int mt = 0; mt < MT; mt++) {
            if (!TA) {
                int r = wm + mt * 16 + (lane & 15);
                int g = 2 * s + (lane >> 4);
                aA[s][mt] = r * 128 + ((g ^ (r & 7)) << 4);
            } else {
                int k = 16 * s + (lane & 7) + (lane >> 4) * 8;
                int mg = ((wm + mt * 16) >> 3) + ((lane >> 3) & 1);
                aA[s][mt] = (BM == 64) ? k * 128 + ((mg ^ (k & 7)) << 4)
                                       : k * 64  + ((mg ^ (k & 3)) << 4);
            }
        }
        #pragma unroll
        for (int j = 0; j < 2; j++) {
            if (!TB) {
                int k = 16 * s + (lane & 7) + ((lane >> 3) & 1) * 8;
                int ng = ((wn + j * 16) >> 3) + (lane >> 4);
                aB[s][j] = A_T + k * 256 + ((ng ^ (k & 7)) << 4);
            } else {
                int n = wn + j * 16 + (lane & 7) + (lane >> 4) * 8;
                int g = 2 * s + ((lane >> 3) & 1);
                aB[s][j] = A_T + n * 128 + ((g ^ (n & 7)) << 4);
            }
        }
    }

    const int NC = K >> 6;

    auto issue = [&](int c, int buf) {
        uint32_t b = sbase + buf * BUF;
        #pragma unroll
        for (int i = 0; i < ACP; i++) cp16(b + dA[i], srcA[i] + c * advA);
        #pragma unroll
        for (int i = 0; i < 4;   i++) cp16(b + dB[i], srcB[i] + c * advB);
        asm volatile("cp.async.commit_group;");
    };

    issue(0, 0);
    issue(1, 1);

    // L2 prefetch of epilogue operands (overlaps the whole k-loop)
    if ((lane & 3) == 0) {
        #pragma unroll
        for (int mt = 0; mt < MT; mt++) {
            #pragma unroll
            for (int half = 0; half < 2; half++) {
                int r = m0 + wm + mt * 16 + (lane >> 2) + half * 8;
                size_t off = (size_t)r * ldc + n0 + wn;
                if (EPI == 6) {
                    pref_l2(C + off);
                    pref_l2(S + off);
                } else if (EPI == 4 || EPI == 5) {
                    pref_l2(aux + off);
                }
            }
        }
    }

    for (int c = 0; c < NC; c++) {
        if (c < NC - 1) asm volatile("cp.async.wait_group 1;");
        else            asm volatile("cp.async.wait_group 0;");
        __syncthreads();
        if (c + 2 < NC) issue(c + 2, (c + 2) % 3);

        const uint32_t bb = sbase + (c % 3) * BUF;
        uint32_t FA[4][MT][4], FB[4][4][2];
        #pragma unroll
        for (int s = 0; s < 4; s++) {
            #pragma unroll
            for (int mt = 0; mt < MT; mt++) {
                if (!TA) ldsm4 (bb + aA[s][mt], FA[s][mt][0], FA[s][mt][1], FA[s][mt][2], FA[s][mt][3]);
                else     ldsm4t(bb + aA[s][mt], FA[s][mt][0], FA[s][mt][1], FA[s][mt][2], FA[s][mt][3]);
            }
            #pragma unroll
            for (int j = 0; j < 2; j++) {
                if (!TB) ldsm4t(bb + aB[s][j], FB[s][2*j][0], FB[s][2*j][1], FB[s][2*j+1][0], FB[s][2*j+1][1]);
                else     ldsm4 (bb + aB[s][j], FB[s][2*j][0], FB[s][2*j][1], FB[s][2*j+1][0], FB[s][2*j+1][1]);
            }
        }
        #pragma unroll
        for (int s = 0; s < 4; s++)
            #pragma unroll
            for (int mt = 0; mt < MT; mt++)
                #pragma unroll
                for (int nt = 0; nt < 4; nt++)
                    mma16816(acc[mt][nt], FA[s][mt], FB[s][nt]);
    }
    __syncthreads();

    #pragma unroll
    for (int mt = 0; mt < MT; mt++) {
        #pragma unroll
        for (int half = 0; half < 2; half++) {
            int r = m0 + wm + mt * 16 + (lane >> 2) + half * 8;
            #pragma unroll
            for (int nt = 0; nt < 4; nt++) {
                int cc = n0 + wn + nt * 8 + 2 * (lane & 3);
                float v0 = acc[mt][nt][half * 2 + 0];
                float v1 = acc[mt][nt][half * 2 + 1];
                size_t idx = (size_t)r * ldc + cc;
                if (EPI == 0) {
                    *(float2*)(C + idx) = make_float2(v0, v1);
                } else if (EPI == 1) {
                    *(uint32_t*)(Ch + idx) = pack_h2(v0, v1);
                } else if (EPI == 3) {
                    *(float2*)(C + idx) = make_float2(v0, v1);
                    *(uint32_t*)(Ch + idx) = pack_h2(gelu_f(v0), gelu_f(v1));
                } else if (EPI == 4) {
                    float2 a2 = *(const float2*)(aux + idx);
                    *(uint32_t*)(Ch + idx) = pack_h2((v0 - a2.x) * scale, (v1 - a2.y) * scale);
                } else if (EPI == 5) {
                    float2 a2 = *(const float2*)(aux + idx);
                    *(uint32_t*)(Ch + idx) = pack_h2(v0 * gelu_grad_f(a2.x), v1 * gelu_grad_f(a2.y));
                } else if (EPI == 6) {
                    float2 w = *(const float2*)(C + idx);
                    float2 s = *(const float2*)(S + idx);
                    float s0 = decay * s.x - lr * v0;
                    float s1 = decay * s.y - lr * v1;
                    float w0 = om * w.x + s0, w1 = om * w.y + s1;
                    *(float2*)(S + idx) = make_float2(s0, s1);
                    *(float2*)(C + idx) = make_float2(w0, w1);
                    *(uint32_t*)(Ch + idx) = pack_h2(w0, w1);
                } else if (EPI == 7) {
                    int b = r >> 12, sq = r & 4095, chn = sq >> 8, t = sq & 255;
                    size_t orow = (size_t)(chn * 1024 + b * 256 + t) * ldc + cc;
                    *(uint32_t*)(Ch + orow) = pack_h2(v0, v1);
                } else if (EPI == 8) {
                    int b = r >> 12, sq = r & 4095, chn = sq >> 8, t = sq & 255;
                    size_t orow = (size_t)(chn * 1024 + b * 256 + t) * ldc + cc;
                    *(float2*)(C + orow) = make_float2(v0, v1);
                } else { // EPI == 9
                    *(uint32_t*)(Ch + idx) = pack_h2(gelu_f(v0), gelu_f(v1));
                }
            }
        }
    }
}

// ---------------- standalone wrappers ---------------------------------------
__global__ void __launch_bounds__(256) kv_kernel() {
    extern __shared__ char smem[];
    const uint32_t sbase = smem_u32(smem);
    int m0 = blockIdx.y * 64, n0 = blockIdx.x * 128;
    if (blockIdx.z == 0)
        tile_gemm<64,false,false,7>(g_xh, D_IN, g_wkh, D_IN, D_IN,
            m0, n0, sbase, nullptr, g_Kh, D_IN, nullptr, 0.f, 0.f, 0.f, 0.f, nullptr);
    else
        tile_gemm<64,false,false,8>(g_xh, D_IN, g_wvh, D_IN, D_IN,
            m0, n0, sbase, g_V, nullptr, D_IN, nullptr, 0.f, 0.f, 0.f, 0.f, nullptr);
}

__global__ void __launch_bounds__(256) m1_kernel() {
    extern __shared__ char smem[];
    const uint32_t sbase = smem_u32(smem);
    tile_gemm<64,false,false,1>(g_wqh, D_IN, g_W1h, HID, D_IN,
        blockIdx.y * 64, blockIdx.x * 128, sbase,
        nullptr, g_M1h, HID, nullptr, 0.f, 0.f, 0.f, 0.f, nullptr);
}

__global__ void __launch_bounds__(256) ro1_kernel() {
    extern __shared__ char smem[];
    const uint32_t sbase = smem_u32(smem);
    tile_gemm<64,false,false,9>(g_xh, D_IN, g_M1h, HID, D_IN,
        blockIdx.y * 64, blockIdx.x * 128, sbase,
        nullptr, g_Hqh, HID, nullptr, 0.f, 0.f, 0.f, 0.f, nullptr);
}

__global__ void __launch_bounds__(256) ro2_kernel(float* __restrict__ out) {
    extern __shared__ char smem[];
    const uint32_t sbase = smem_u32(smem);
    tile_gemm<64,false,false,0>(g_Hqh, HID, g_W2hA, D_IN, HID,
        blockIdx.y * 64, blockIdx.x * 128, sbase,
        out, nullptr, D_IN, nullptr, 0.f, 0.f, 0.f, 0.f, nullptr);
}

// ---------------- software grid barrier ---------------------------------------
__device__ __forceinline__ void gsync(unsigned& epoch) {
    __syncthreads();
    if (threadIdx.x == 0) {
        __threadfence();
        epoch++;
        atomicAdd(&g_arrive, 1u);
        const unsigned target = epoch * NB;
        while (__ldcg(&g_arrive) < target) __nanosleep(32);
        __threadfence();
    }
    __syncthreads();
}

// ---------------- persistent chunk loop ---------------------------------------
__global__ void __launch_bounds__(256, 1)
chunk_loop(const float* __restrict__ alpha_t, const float* __restrict__ lr_t,
           const float* __restrict__ decay_t, const int* __restrict__ upd)
{
    if (*upd == 0) return;
    const float alpha = sigmoid_f(*alpha_t);
    const float lr    = sigmoid_f(*lr_t);
    const float decay = sigmoid_f(*decay_t);
    const float om    = 1.0f - alpha;
    const float escale = 2.0f / (float)(ROWS_CHUNK * D_IN);

    extern __shared__ char smem[];
    const uint32_t sbase = smem_u32(smem);
    unsigned epoch = 0;

    for (int c = 0; c < NCHUNK; c++) {
        const __half* Kch = g_Kh + (size_t)c * ROWS_CHUNK * D_IN;
        const float*  Vc  = g_V  + (size_t)c * ROWS_CHUNK * D_IN;
        __half* W2cur = (c & 1) ? g_W2hB : g_W2hA;
        __half* W2nxt = (c & 1) ? g_W2hA : g_W2hB;

        for (int t = blockIdx.x; t < 128; t += NB)
            tile_gemm<64,false,false,3>(Kch, D_IN, g_W1h, HID, D_IN,
                (t >> 3) * 64, (t & 7) * 128, sbase,
                g_H, g_Ah, HID, nullptr, 0.f, 0.f, 0.f, 0.f, nullptr);
        gsync(epoch);

        for (int t = blockIdx.x; t < 128; t += NB)
            tile_gemm<32,false,false,4>(g_Ah, HID, W2cur, D_IN, HID,
                (t >> 2) * 32, (t & 3) * 128, sbase,
                nullptr, g_Eh, D_IN, Vc, escale, 0.f, 0.f, 0.f, nullptr);
        gsync(epoch);

        for (int t = blockIdx.x; t < 256; t += NB) {
            if (t < 128)
                tile_gemm<64,false,true,5>(g_Eh, D_IN, W2cur, D_IN, D_IN,
                    (t >> 3) * 64, (t & 7) * 128, sbase,
                    nullptr, g_dHh, HID, g_H, 0.f, 0.f, 0.f, 0.f, nullptr);
            else {
                int u = t - 128;
                tile_gemm<32,true,false,6>(g_Ah, HID, g_Eh, D_IN, ROWS_CHUNK,
                    (u >> 2) * 32, (u & 3) * 128, sbase,
                    g_W2, W2nxt, D_IN, nullptr, 0.f, decay, lr, om, g_S2);
            }
        }
        gsync(epoch);

        for (int t = blockIdx.x; t < 128; t += NB)
            tile_gemm<32,true,false,6>(Kch, D_IN, g_dHh, HID, ROWS_CHUNK,
                (t >> 3) * 32, (t & 7) * 128, sbase,
                g_W1, g_W1h, HID, nullptr, 0.f, decay, lr, om, g_S1);
        gsync(epoch);
    }
}

// ---------------- init / convert kernels -------------------------------------
__global__ void convert_all(const float* __restrict__ x,
                            const float* __restrict__ wq,
                            const float* __restrict__ wk,
                            const float* __restrict__ wv) {
    const int NX = ROWS_TOTAL * D_IN / 4;
    const int NW = D_IN * D_IN / 4;
    int i = blockIdx.x * 256 + threadIdx.x;
    const float* src;
    __half* dst;
    int j;
    if (i < NX)               { src = x;  dst = g_xh;  j = i; }
    else if (i < NX + NW)     { src = wq; dst = g_wqh; j = i - NX; }
    else if (i < NX + 2 * NW) { src = wk; dst = g_wkh; j = i - NX - NW; }
    else if (i < NX + 3 * NW) { src = wv; dst = g_wvh; j = i - NX - 2 * NW; }
    else return;
    float4 v = ((const float4*)src)[j];
    ((uint2*)dst)[j] = make_uint2(pack_h2(v.x, v.y), pack_h2(v.z, v.w));
}
__global__ void init_kernel(const float* __restrict__ w1, const float* __restrict__ w2) {
    int i = blockIdx.x * 256 + threadIdx.x;
    if (i == 0) g_arrive = 0;
    if (i < WSZ) {
        float a = w1[i], b = w2[i];
        g_W1[i] = a; g_W2[i] = b;
        g_S1[i] = 0.f; g_S2[i] = 0.f;
        g_W1h[i]  = __float2half_rn(a);
        g_W2hA[i] = __float2half_rn(b);
    }
}

// ---------------- launcher ----------------------------------------------------
extern "C" void kernel_launch(void* const* d_in, const int* in_sizes, int n_in,
                              void* d_out, int out_size)
{
    const float* x       = (const float*)d_in[0];
    const float* w_q     = (const float*)d_in[1];
    const float* w_k     = (const float*)d_in[2];
    const float* w_v     = (const float*)d_in[3];
    const float* mem_w1  = (const float*)d_in[4];
    const float* mem_w2  = (const float*)d_in[5];
    const float* alpha_t = (const float*)d_in[6];
    const float* lr_t    = (const float*)d_in[7];
    const float* decay_t = (const float*)d_in[8];
    const int*   upd     = (const int*)d_in[9];
    float* out = (float*)d_out;

    cudaFuncSetAttribute(kv_kernel,  cudaFuncAttributeMaxDynamicSharedMemorySize, P_SMEM);
    cudaFuncSetAttribute(m1_kernel,  cudaFuncAttributeMaxDynamicSharedMemorySize, P_SMEM);
    cudaFuncSetAttribute(ro1_kernel, cudaFuncAttributeMaxDynamicSharedMemorySize, P_SMEM);
    cudaFuncSetAttribute(ro2_kernel, cudaFuncAttributeMaxDynamicSharedMemorySize, P_SMEM);
    cudaFuncSetAttribute(chunk_loop, cudaFuncAttributeMaxDynamicSharedMemorySize, P_SMEM);

    const dim3 thr(256);

    {
        const int NX = ROWS_TOTAL * D_IN / 4;
        const int NW = D_IN * D_IN / 4;
        int total = NX + 3 * NW;
        convert_all<<<(total + 255) / 256, thr>>>(x, w_q, w_k, w_v);
    }
    init_kernel<<<WSZ / 256, thr>>>(mem_w1, mem_w2);

    kv_kernel<<<dim3(D_IN / 128, ROWS_TOTAL / 64, 2), thr, P_SMEM>>>();

    chunk_loop<<<NB, thr, P_SMEM>>>(alpha_t, lr_t, decay_t, upd);

    m1_kernel<<<dim3(HID / 128, D_IN / 64), thr, P_SMEM>>>();
    ro1_kernel<<<dim3(HID / 128, ROWS_TOTAL / 64), thr, P_SMEM>>>();
    ro2_kernel<<<dim3(D_IN / 128, ROWS_TOTAL / 64), thr, P_SMEM>>>(out);

    (void)in_sizes; (void)n_in; (void)out_size;
}